// round 15
// baseline (speedup 1.0000x reference)
#include <cuda_runtime.h>
#include <math.h>

// Problem constants
#define S_LEN 128
#define B_SZ  32
#define D_MOD 256
#define H_SZ  512
#define T_LEN 64
#define TDEC  63
#define VT_SZ 32000

typedef unsigned long long ull;

// ---------------- packed fp32x2 helpers (encoder persistent kernel only) ----------------
__device__ __forceinline__ ull pk2(float lo, float hi){
    ull r; asm("mov.b64 %0, {%1, %2};" : "=l"(r) : "f"(lo), "f"(hi)); return r;
}
__device__ __forceinline__ void ffma2(ull &d, ull a, ull b){
    asm("fma.rn.f32x2 %0, %1, %2, %0;" : "+l"(d) : "l"(a), "l"(b));
}
__device__ __forceinline__ float2 upk(ull v){
    float2 f; asm("mov.b64 {%0, %1}, %2;" : "=f"(f.x), "=f"(f.y) : "l"(v)); return f;
}
__device__ __forceinline__ ull addp(ull a, ull b){
    ull r; asm("add.rn.f32x2 %0, %1, %2;" : "=l"(r) : "l"(a), "l"(b)); return r;
}
__device__ __forceinline__ unsigned f2tf32(float f){
    unsigned u; asm("cvt.rna.tf32.f32 %0, %1;" : "=r"(u) : "f"(f)); return u;
}

// ---------------- scratch (device globals; no allocation allowed) ----------------
__device__ float g_emb  [4096*256];
__device__ float g_bufA [4096*512];
__device__ float g_bufB [4096*512];
__device__ float g_Xg   [2*4096*1024];
__device__ float g_WhhT [6*16*256*64];
__device__ float g_he   [2][2*32*256];
__device__ float g_ce   [2*32*256];
__device__ float g_hdec [3*32*512];
__device__ float g_cdec [3*32*512];
__device__ float g_embd [2048*512];
__device__ float g_Xd0  [2048*2048];
__device__ float g_Wcat0 [2048*1024];
__device__ float g_Wcat12[2*2048*1024];
__device__ float g_P    [4096*512];
__device__ float g_xc0  [32*1024];
__device__ float g_xc1  [32*1024];
__device__ float g_xc2  [32*1024];
__device__ float g_hTop [32*512];
__device__ float g_Gp   [8*32*2048];
__device__ float g_Htop [2048*512];

__device__ unsigned int g_barc[8*32];

__device__ __forceinline__ float sigm(float x){ return 1.f/(1.f+expf(-x)); }

// ---------------- setup kernels ----------------
__global__ void k_embed_src(const int* __restrict__ x, const float* __restrict__ emb){
    int idx = blockIdx.x*blockDim.x + threadIdx.x;
    int d = idx & 255; int sb = idx >> 8; int b = sb & 31; int s = sb >> 5;
    g_emb[idx] = emb[(size_t)x[b*S_LEN + s]*D_MOD + d];
}

__global__ void k_embed_tgt(const int* __restrict__ y, const float* __restrict__ emb){
    int idx = blockIdx.x*blockDim.x + threadIdx.x;
    int u = idx & 511; int tb = idx >> 9; int b = tb & 31; int t = tb >> 5;
    g_embd[idx] = emb[(size_t)y[b*T_LEN + t]*H_SZ + u];
}

__global__ void k_trans_whh(const float* __restrict__ we0, const float* __restrict__ we12){
    int idx = blockIdx.x*blockDim.x + threadIdx.x;
    int mat = idx >> 18; int rem = idx & 262143;
    int jt = (rem >> 14) & 15;
    int k  = (rem >> 6) & 255;
    int g  = (rem >> 4) & 3;
    int jj = rem & 15;
    int n = g*256 + jt*16 + jj;
    const float* src = (mat < 2) ? (we0 + (size_t)mat*1024*256)
                                 : (we12 + (size_t)(mat-2)*1024*256);
    g_WhhT[idx] = src[n*256 + k];
}

__global__ void k_build_wcat(const float* __restrict__ wih0, const float* __restrict__ whh0,
                             const float* __restrict__ wih12, const float* __restrict__ whh12){
    int idx = blockIdx.x*blockDim.x + threadIdx.x;
    int m = idx / (2048*1024); int rem = idx % (2048*1024);
    int n = rem >> 10; int c = rem & 1023;
    if (m == 0){
        g_Wcat0[rem] = (c < 512) ? wih0[n*1024 + 512 + c] : whh0[n*512 + (c-512)];
    } else {
        int l = m - 1;
        float v = (c < 512) ? wih12[((size_t)l*2048 + n)*512 + c]
                            : whh12[((size_t)l*2048 + n)*512 + (c-512)];
        g_Wcat12[((size_t)l*2048 + n)*1024 + c] = v;
    }
}

__global__ void k_zero_hc(){
    int i = blockIdx.x*blockDim.x + threadIdx.x;
    if (i < 2*32*256){ g_he[0][i]=0.f; g_he[1][i]=0.f; g_ce[i]=0.f; }
}

// ---------------- generalized tf32 MMA GEMM, 128x128 tile (proven pattern from head) ----------------
__global__ __launch_bounds__(256) void k_mma_gemm(
    float* __restrict__ C, const float* __restrict__ A, const float* __restrict__ W,
    const float* __restrict__ bias, int M, int K, int lda, int ldw, int ldc)
{
    __shared__ unsigned As[128*36];
    __shared__ unsigned Ws[128*36];
    int bm = blockIdx.y*128, bn = blockIdx.x*128;
    int tid = threadIdx.x;
    int lane = tid & 31, warp = tid >> 5;
    int g = lane >> 2, tig = lane & 3;
    int wm = (warp & 3)*32, wn = (warp >> 2)*64;
    float acc[2][8][4];
    #pragma unroll
    for (int mt=0;mt<2;mt++)
        #pragma unroll
        for (int nt=0;nt<8;nt++)
            #pragma unroll
            for (int q=0;q<4;q++) acc[mt][nt][q]=0.f;

    for (int kc = 0; kc < K; kc += 32){
        #pragma unroll
        for (int q=0;q<4;q++){
            int idx = tid + q*256;
            int row = idx >> 3, c4 = (idx & 7)*4;
            float4 v = make_float4(0.f,0.f,0.f,0.f);
            if (bm + row < M)
                v = *reinterpret_cast<const float4*>(A + (size_t)(bm+row)*lda + kc + c4);
            unsigned* d = As + row*36 + c4;
            d[0]=f2tf32(v.x); d[1]=f2tf32(v.y); d[2]=f2tf32(v.z); d[3]=f2tf32(v.w);
        }
        #pragma unroll
        for (int q=0;q<4;q++){
            int idx = tid + q*256;
            int row = idx >> 3, c4 = (idx & 7)*4;
            float4 v = *reinterpret_cast<const float4*>(W + (size_t)(bn+row)*ldw + kc + c4);
            unsigned* d = Ws + row*36 + c4;
            d[0]=f2tf32(v.x); d[1]=f2tf32(v.y); d[2]=f2tf32(v.z); d[3]=f2tf32(v.w);
        }
        __syncthreads();
        #pragma unroll
        for (int k8 = 0; k8 < 32; k8 += 8){
            unsigned a[2][4], bf[8][2];
            #pragma unroll
            for (int mt=0;mt<2;mt++){
                int rb = wm + mt*16;
                a[mt][0] = As[(rb+g  )*36 + k8 + tig];
                a[mt][1] = As[(rb+g+8)*36 + k8 + tig];
                a[mt][2] = As[(rb+g  )*36 + k8 + tig + 4];
                a[mt][3] = As[(rb+g+8)*36 + k8 + tig + 4];
            }
            #pragma unroll
            for (int nt=0;nt<8;nt++){
                int nb = wn + nt*8 + g;
                bf[nt][0] = Ws[nb*36 + k8 + tig];
                bf[nt][1] = Ws[nb*36 + k8 + tig + 4];
            }
            #pragma unroll
            for (int mt=0;mt<2;mt++)
                #pragma unroll
                for (int nt=0;nt<8;nt++){
                    asm("mma.sync.aligned.m16n8k8.row.col.f32.tf32.tf32.f32 "
                        "{%0,%1,%2,%3}, {%4,%5,%6,%7}, {%8,%9}, {%0,%1,%2,%3};"
                        : "+f"(acc[mt][nt][0]),"+f"(acc[mt][nt][1]),
                          "+f"(acc[mt][nt][2]),"+f"(acc[mt][nt][3])
                        : "r"(a[mt][0]),"r"(a[mt][1]),"r"(a[mt][2]),"r"(a[mt][3]),
                          "r"(bf[nt][0]),"r"(bf[nt][1]));
                }
        }
        __syncthreads();
    }
    #pragma unroll
    for (int mt=0;mt<2;mt++){
        #pragma unroll
        for (int nt=0;nt<8;nt++){
            int col = bn + wn + nt*8 + 2*tig;
            float bx = bias ? bias[col] : 0.f;
            float by = bias ? bias[col+1] : 0.f;
            int r0 = bm + wm + mt*16 + g;
            int r1 = r0 + 8;
            if (r0 < M){
                C[(size_t)r0*ldc + col]   = acc[mt][nt][0] + bx;
                C[(size_t)r0*ldc + col+1] = acc[mt][nt][1] + by;
            }
            if (r1 < M){
                C[(size_t)r1*ldc + col]   = acc[mt][nt][2] + bx;
                C[(size_t)r1*ldc + col+1] = acc[mt][nt][3] + by;
            }
        }
    }
}

// ---------------- tf32 head GEMM, 128x128 tile (proven R14), permuted store ----------------
__global__ __launch_bounds__(256) void k_head_mma(
    float* __restrict__ C, const float* __restrict__ A, const float* __restrict__ W,
    const float* __restrict__ bias)
{
    __shared__ unsigned As[128*36];
    __shared__ unsigned Ws[128*36];
    int bm = blockIdx.y*128, bn = blockIdx.x*128;
    int tid = threadIdx.x;
    int lane = tid & 31, warp = tid >> 5;
    int g = lane >> 2, tig = lane & 3;
    int wm = (warp & 3)*32, wn = (warp >> 2)*64;
    float acc[2][8][4];
    #pragma unroll
    for (int mt=0;mt<2;mt++)
        #pragma unroll
        for (int nt=0;nt<8;nt++)
            #pragma unroll
            for (int q=0;q<4;q++) acc[mt][nt][q]=0.f;

    for (int kc = 0; kc < 512; kc += 32){
        #pragma unroll
        for (int q=0;q<4;q++){
            int idx = tid + q*256;
            int row = idx >> 3, c4 = (idx & 7)*4;
            float4 v = make_float4(0.f,0.f,0.f,0.f);
            if (bm + row < 2016)
                v = *reinterpret_cast<const float4*>(A + (size_t)(bm+row)*512 + kc + c4);
            unsigned* d = As + row*36 + c4;
            d[0]=f2tf32(v.x); d[1]=f2tf32(v.y); d[2]=f2tf32(v.z); d[3]=f2tf32(v.w);
        }
        #pragma unroll
        for (int q=0;q<4;q++){
            int idx = tid + q*256;
            int row = idx >> 3, c4 = (idx & 7)*4;
            float4 v = *reinterpret_cast<const float4*>(W + (size_t)(bn+row)*512 + kc + c4);
            unsigned* d = Ws + row*36 + c4;
            d[0]=f2tf32(v.x); d[1]=f2tf32(v.y); d[2]=f2tf32(v.z); d[3]=f2tf32(v.w);
        }
        __syncthreads();
        #pragma unroll
        for (int k8 = 0; k8 < 32; k8 += 8){
            unsigned a[2][4], bf[8][2];
            #pragma unroll
            for (int mt=0;mt<2;mt++){
                int rb = wm + mt*16;
                a[mt][0] = As[(rb+g  )*36 + k8 + tig];
                a[mt][1] = As[(rb+g+8)*36 + k8 + tig];
                a[mt][2] = As[(rb+g  )*36 + k8 + tig + 4];
                a[mt][3] = As[(rb+g+8)*36 + k8 + tig + 4];
            }
            #pragma unroll
            for (int nt=0;nt<8;nt++){
                int nb = wn + nt*8 + g;
                bf[nt][0] = Ws[nb*36 + k8 + tig];
                bf[nt][1] = Ws[nb*36 + k8 + tig + 4];
            }
            #pragma unroll
            for (int mt=0;mt<2;mt++)
                #pragma unroll
                for (int nt=0;nt<8;nt++){
                    asm("mma.sync.aligned.m16n8k8.row.col.f32.tf32.tf32.f32 "
                        "{%0,%1,%2,%3}, {%4,%5,%6,%7}, {%8,%9}, {%0,%1,%2,%3};"
                        : "+f"(acc[mt][nt][0]),"+f"(acc[mt][nt][1]),
                          "+f"(acc[mt][nt][2]),"+f"(acc[mt][nt][3])
                        : "r"(a[mt][0]),"r"(a[mt][1]),"r"(a[mt][2]),"r"(a[mt][3]),
                          "r"(bf[nt][0]),"r"(bf[nt][1]));
                }
        }
        __syncthreads();
    }
    #pragma unroll
    for (int mt=0;mt<2;mt++){
        #pragma unroll
        for (int nt=0;nt<8;nt++){
            int col = bn + wn + nt*8 + 2*tig;
            float bx = bias[col], by = bias[col+1];
            int r0 = bm + wm + mt*16 + g;
            int r1 = r0 + 8;
            if (r0 < 2016){
                int rr = (r0 & 31)*TDEC + (r0 >> 5);
                C[(size_t)rr*VT_SZ + col]   = acc[mt][nt][0] + bx;
                C[(size_t)rr*VT_SZ + col+1] = acc[mt][nt][1] + by;
            }
            if (r1 < 2016){
                int rr = (r1 & 31)*TDEC + (r1 >> 5);
                C[(size_t)rr*VT_SZ + col]   = acc[mt][nt][2] + bx;
                C[(size_t)rr*VT_SZ + col+1] = acc[mt][nt][3] + by;
            }
        }
    }
}

// ---------------- persistent encoder layer (proven R5) ----------------
#define ENC_SMEM_FLOATS (16384 + 2048 + 2048 + 512)
__global__ __launch_bounds__(256) void k_enc_layer(const float* __restrict__ WT,
                                                   float* __restrict__ out)
{
    extern __shared__ float dyn[];
    float* ws   = dyn;
    float* hstf = dyn + 16384;
    ull*   psum = (ull*)(dyn + 16384 + 2048);
    float* sgf  = dyn + 16384 + 2048 + 2048;

    int jt = blockIdx.x, dir = blockIdx.y, bb = blockIdx.z;
    int tid = threadIdx.x;
    const float* Wg = WT + (size_t)dir*262144 + (size_t)jt*16384;
    for (int i = tid; i < 16384; i += 256) ws[i] = Wg[i];

    int gid = dir*4 + bb;
    unsigned* bcnt = &g_barc[gid*32];
    volatile unsigned* bgen = (volatile unsigned*)&g_barc[gid*32 + 16];

    int col1 = tid & 63, kq = tid >> 6;
    int col2 = tid >> 2, pr = tid & 3;
    int jj = tid >> 3, b = tid & 7;
    int bglob = bb*8 + b;
    int j = jt*16 + jj;
    float creg = 0.f;
    __syncthreads();

    for (int t = 0; t < S_LEN; t++){
        int cur = t & 1, nxt = cur ^ 1;
        int tt = dir ? (S_LEN-1-t) : t;
        #pragma unroll
        for (int q = 0; q < 8; q++){
            hstf[tid*8 + q] = __ldcg(&g_he[cur][(dir*32 + bb*8 + q)*256 + tid]);
        }
        __syncthreads();
        {
            const float* wp = ws + col1;
            const ulonglong2* hp = (const ulonglong2*)hstf;
            ull a0=0,a1=0,a2=0,a3=0;
            #pragma unroll 8
            for (int kk = 0; kk < 64; kk++){
                int k = kq*64 + kk;
                float w = wp[k*64];
                ull w2 = pk2(w, w);
                ulonglong2 hA = hp[k*2], hB = hp[k*2+1];
                ffma2(a0, w2, hA.x); ffma2(a1, w2, hA.y);
                ffma2(a2, w2, hB.x); ffma2(a3, w2, hB.y);
            }
            ull* pp = psum + ((size_t)kq*64 + col1)*4;
            pp[0]=a0; pp[1]=a1; pp[2]=a2; pp[3]=a3;
        }
        __syncthreads();
        {
            ull s = psum[(0*64+col2)*4+pr];
            s = addp(s, psum[(1*64+col2)*4+pr]);
            s = addp(s, psum[(2*64+col2)*4+pr]);
            s = addp(s, psum[(3*64+col2)*4+pr]);
            ((ull*)sgf)[col2*4+pr] = s;
        }
        __syncthreads();
        if (tid < 128){
            float gi = sgf[(0*16+jj)*8 + b];
            float gf = sgf[(1*16+jj)*8 + b];
            float gg = sgf[(2*16+jj)*8 + b];
            float go = sgf[(3*16+jj)*8 + b];
            const float* xg = g_Xg + ((size_t)(dir*S_LEN + tt)*32 + bglob)*1024;
            gi += xg[j]; gf += xg[256+j]; gg += xg[512+j]; go += xg[768+j];
            float c2 = sigm(gf)*creg + sigm(gi)*tanhf(gg);
            float h2 = sigm(go)*tanhf(c2);
            creg = c2;
            __stcg(&g_he[nxt][(dir*32+bglob)*256 + j], h2);
            out[((size_t)tt*32 + bglob)*512 + dir*256 + j] = h2;
        }
        __threadfence();
        __syncthreads();
        if (tid == 0){
            unsigned gen = *bgen;
            if (atomicAdd(bcnt, 1u) == 15u){
                *bcnt = 0;
                __threadfence();
                *bgen = gen + 1u;
            } else {
                while (*bgen == gen) __nanosleep(32);
            }
        }
        __syncthreads();
    }
    if (tid < 128) g_ce[(dir*32+bglob)*256 + j] = creg;
}

__global__ void k_extract(int l){
    int b = blockIdx.x, tid = threadIdx.x;
    int dir = tid >> 8, jj = tid & 255;
    g_hdec[((size_t)l*32 + b)*512 + tid] = g_he[0][(dir*32+b)*256 + jj];
    g_cdec[((size_t)l*32 + b)*512 + tid] = g_ce[(dir*32+b)*256 + jj];
}

__global__ void k_dec_init(){
    int b = blockIdx.x, u = threadIdx.x;
    g_xc0[b*1024 + 512 + u] = g_hdec[(0*32+b)*512 + u];
    g_xc1[b*1024 + 512 + u] = g_hdec[(1*32+b)*512 + u];
    float h2 = g_hdec[(2*32+b)*512 + u];
    g_xc2[b*1024 + 512 + u] = h2;
    g_hTop[b*512 + u] = h2;
}

// ---------------- decoder attention, fused with previous step's layer-2 LSTM epilogue ----------------
// Block b: if t>0, reduce layer-2 gate partials (from step t-1's gemm2) for batch b,
// apply LSTM, write cstate/xc2-h-half/Htop[t-1], keep h in smem; then attention on h.
__global__ __launch_bounds__(256) void k_attn(const float* __restrict__ P,
                                              const float* __restrict__ enc,
                                              const float* __restrict__ bias2, int t)
{
    int b = blockIdx.x, tid = threadIdx.x;
    __shared__ float hsh[512], ssh[128], red[12];
    if (t > 0){
        for (int u = tid; u < 512; u += 256){
            float gi=0.f, gf=0.f, gg=0.f, go=0.f;
            #pragma unroll
            for (int p=0;p<8;p++){
                const float* g = g_Gp + (size_t)(p*32+b)*2048;
                gi += g[u]; gf += g[512+u]; gg += g[1024+u]; go += g[1536+u];
            }
            gi += bias2[u]; gf += bias2[512+u]; gg += bias2[1024+u]; go += bias2[1536+u];
            int ci = 2*32*512 + b*512 + u;
            float cv = g_cdec[ci];
            float c2 = sigm(gf)*cv + sigm(gi)*tanhf(gg);
            float h2 = sigm(go)*tanhf(c2);
            g_cdec[ci] = c2;
            g_xc2[b*1024 + 512 + u] = h2;
            g_Htop[((size_t)(t-1)*32 + b)*512 + u] = h2;
            hsh[u] = h2;
        }
    } else {
        hsh[tid]     = g_hTop[b*512 + tid];
        hsh[256+tid] = g_hTop[b*512 + 256 + tid];
    }
    __syncthreads();
    int warp = tid >> 5, lane = tid & 31;
    for (int s = warp; s < 128; s += 8){
        const float* p = P + ((size_t)s*32 + b)*512;
        float acc = 0.f;
        for (int i = lane; i < 512; i += 32) acc += hsh[i]*p[i];
        #pragma unroll
        for (int o=16;o>0;o>>=1) acc += __shfl_xor_sync(0xffffffffu, acc, o);
        if (lane == 0) ssh[s] = acc;
    }
    __syncthreads();
    float m = -1e30f;
    if (tid < 128) m = ssh[tid];
    #pragma unroll
    for (int o=16;o>0;o>>=1) m = fmaxf(m, __shfl_xor_sync(0xffffffffu, m, o));
    if (tid < 128 && lane == 0) red[warp] = m;
    __syncthreads();
    float mx = fmaxf(fmaxf(red[0],red[1]), fmaxf(red[2],red[3]));
    float ev = (tid < 128) ? expf(ssh[tid] - mx) : 0.f;
    float sum = ev;
    #pragma unroll
    for (int o=16;o>0;o>>=1) sum += __shfl_xor_sync(0xffffffffu, sum, o);
    if (tid < 128 && lane == 0) red[8+warp] = sum;
    __syncthreads();
    float tot = red[8]+red[9]+red[10]+red[11];
    if (tid < 128) ssh[tid] = ev / tot;
    __syncthreads();
    float c0=0.f, c1=0.f;
    for (int s=0;s<128;s++){
        float a = ssh[s];
        const float* e = enc + ((size_t)s*32 + b)*512;
        c0 += a*e[tid]; c1 += a*e[256+tid];
    }
    g_xc0[b*1024 + tid]       = c0;
    g_xc0[b*1024 + 256 + tid] = c1;
}

// ---------------- skinny decoder gate GEMM via tf32 MMA (K-split, 256 blocks; proven R11) ----------------
__global__ __launch_bounds__(256) void k_skinny_mma(const float* __restrict__ A,
                                                    const float* __restrict__ W)
{
    __shared__ unsigned As[32*36];
    __shared__ unsigned Ws[64*36];
    int ntile = blockIdx.x;
    int p     = blockIdx.y;
    int tid = threadIdx.x;
    int lane = tid & 31, warp = tid >> 5;
    int g = lane >> 2, tig = lane & 3;
    float acc[2][4];
    #pragma unroll
    for (int mt=0;mt<2;mt++)
        #pragma unroll
        for (int q=0;q<4;q++) acc[mt][q]=0.f;

    int n0 = ntile*64, k0 = p*128;
    const float* Wbase = W + (size_t)n0*1024;

    for (int kc = 0; kc < 128; kc += 32){
        {
            int row = tid >> 3, c4 = (tid & 7)*4;
            float4 v = *reinterpret_cast<const float4*>(A + (size_t)row*1024 + k0 + kc + c4);
            unsigned* d = As + row*36 + c4;
            d[0]=f2tf32(v.x); d[1]=f2tf32(v.y); d[2]=f2tf32(v.z); d[3]=f2tf32(v.w);
        }
        #pragma unroll
        for (int q=0;q<2;q++){
            int idx = tid + q*256;
            int row = idx >> 3, c4 = (idx & 7)*4;
            float4 v = *reinterpret_cast<const float4*>(Wbase + (size_t)row*1024 + k0 + kc + c4);
            unsigned* d = Ws + row*36 + c4;
            d[0]=f2tf32(v.x); d[1]=f2tf32(v.y); d[2]=f2tf32(v.z); d[3]=f2tf32(v.w);
        }
        __syncthreads();
        #pragma unroll
        for (int k8 = 0; k8 < 32; k8 += 8){
            unsigned a[2][4], bf[2];
            #pragma unroll
            for (int mt=0;mt<2;mt++){
                int rb = mt*16;
                a[mt][0] = As[(rb+g  )*36 + k8 + tig];
                a[mt][1] = As[(rb+g+8)*36 + k8 + tig];
                a[mt][2] = As[(rb+g  )*36 + k8 + tig + 4];
                a[mt][3] = As[(rb+g+8)*36 + k8 + tig + 4];
            }
            int nb = warp*8 + g;
            bf[0] = Ws[nb*36 + k8 + tig];
            bf[1] = Ws[nb*36 + k8 + tig + 4];
            #pragma unroll
            for (int mt=0;mt<2;mt++){
                asm("mma.sync.aligned.m16n8k8.row.col.f32.tf32.tf32.f32 "
                    "{%0,%1,%2,%3}, {%4,%5,%6,%7}, {%8,%9}, {%0,%1,%2,%3};"
                    : "+f"(acc[mt][0]),"+f"(acc[mt][1]),
                      "+f"(acc[mt][2]),"+f"(acc[mt][3])
                    : "r"(a[mt][0]),"r"(a[mt][1]),"r"(a[mt][2]),"r"(a[mt][3]),
                      "r"(bf[0]),"r"(bf[1]));
            }
        }
        __syncthreads();
    }
    float* outp = g_Gp + (size_t)p*32*2048;
    int colg = n0 + warp*8 + 2*tig;
    #pragma unroll
    for (int mt=0;mt<2;mt++){
        int r0 = mt*16 + g;
        outp[(size_t)r0*2048 + colg]       = acc[mt][0];
        outp[(size_t)r0*2048 + colg+1]     = acc[mt][1];
        outp[(size_t)(r0+8)*2048 + colg]   = acc[mt][2];
        outp[(size_t)(r0+8)*2048 + colg+1] = acc[mt][3];
    }
}

// ---------------- decoder LSTM elementwise (proven; reduces K-split partials) ----------------
__global__ void k_elem(const float* __restrict__ add, const float* __restrict__ bias,
                       float* __restrict__ c,
                       float* __restrict__ d1, int s1,
                       float* __restrict__ d2, int s2,
                       float* __restrict__ d3, int s3)
{
    int b = blockIdx.x, j = threadIdx.x;
    float gi=0.f, gf=0.f, gg=0.f, go=0.f;
    #pragma unroll
    for (int p=0;p<8;p++){
        const float* g = g_Gp + (size_t)(p*32+b)*2048;
        gi += g[j]; gf += g[512+j]; gg += g[1024+j]; go += g[1536+j];
    }
    if (add){ const float* a = add + (size_t)b*2048; gi+=a[j]; gf+=a[512+j]; gg+=a[1024+j]; go+=a[1536+j]; }
    if (bias){ gi+=bias[j]; gf+=bias[512+j]; gg+=bias[1024+j]; go+=bias[1536+j]; }
    float cv = c[b*512 + j];
    float c2 = sigm(gf)*cv + sigm(gi)*tanhf(gg);
    float h2 = sigm(go)*tanhf(c2);
    c[b*512 + j] = c2;
    d1[b*s1 + j] = h2;
    if (d2) d2[b*s2 + j] = h2;
    if (d3) d3[b*s3 + j] = h2;
}

// ---------------- host orchestration ----------------
static float* symaddr(const void* s){ void* p=nullptr; cudaGetSymbolAddress(&p, s); return (float*)p; }

extern "C" void kernel_launch(void* const* d_in, const int* in_sizes, int n_in,
                              void* d_out, int out_size)
{
    (void)in_sizes; (void)n_in; (void)out_size;
    const int*   x       = (const int*)  d_in[0];
    const int*   y       = (const int*)  d_in[1];
    const float* semb    = (const float*)d_in[2];
    const float* temb    = (const float*)d_in[3];
    const float* Wih_e0  = (const float*)d_in[4];
    const float* Whh_e0  = (const float*)d_in[5];
    const float* b_e0    = (const float*)d_in[6];
    const float* Wih_e12 = (const float*)d_in[7];
    const float* Whh_e12 = (const float*)d_in[8];
    const float* b_e12   = (const float*)d_in[9];
    const float* Wih_d0  = (const float*)d_in[10];
    const float* Whh_d0  = (const float*)d_in[11];
    const float* b_d0    = (const float*)d_in[12];
    const float* Wih_d12 = (const float*)d_in[13];
    const float* Whh_d12 = (const float*)d_in[14];
    const float* b_d12   = (const float*)d_in[15];
    const float* Wa      = (const float*)d_in[16];
    const float* Wout    = (const float*)d_in[17];
    const float* bout    = (const float*)d_in[18];
    float* out = (float*)d_out;

    float* P_emb   = symaddr(g_emb);
    float* P_bufA  = symaddr(g_bufA);
    float* P_bufB  = symaddr(g_bufB);
    float* P_Xg    = symaddr(g_Xg);
    float* P_WhhT  = symaddr(g_WhhT);
    float* P_embd  = symaddr(g_embd);
    float* P_Xd0   = symaddr(g_Xd0);
    float* P_Wcat0 = symaddr(g_Wcat0);
    float* P_Wcat12= symaddr(g_Wcat12);
    float* P_P     = symaddr(g_P);
    float* P_xc0   = symaddr(g_xc0);
    float* P_xc1   = symaddr(g_xc1);
    float* P_xc2   = symaddr(g_xc2);
    float* P_hTop  = symaddr(g_hTop);
    float* P_Htop  = symaddr(g_Htop);
    float* P_cdec  = symaddr(g_cdec);

    const int enc_smem = ENC_SMEM_FLOATS * 4;
    cudaFuncSetAttribute(k_enc_layer, cudaFuncAttributeMaxDynamicSharedMemorySize, enc_smem);

    // ---- setup ----
    k_trans_whh<<<6144,256>>>(Whh_e0, Whh_e12);
    k_build_wcat<<<24576,256>>>(Wih_d0, Whh_d0, Wih_d12, Whh_d12);
    k_embed_src<<<4096,256>>>(x, semb);

    // ---- encoder: 3 bidirectional layers (Xg via widened tf32 MMA) ----
    const float* layerIn = P_emb; int lk = 256;
    float* outBufs[3] = {P_bufA, P_bufB, P_bufA};
    for (int l=0; l<3; l++){
        const float* Wih = (l==0) ? Wih_e0 : (Wih_e12 + (size_t)(l-1)*2*1024*512);
        const float* be  = (l==0) ? b_e0   : (b_e12  + (size_t)(l-1)*2*1024);
        for (int dir=0; dir<2; dir++){
            k_mma_gemm<<<dim3(8,32),256>>>(P_Xg + (size_t)dir*4096*1024, layerIn,
                                           Wih + (size_t)dir*1024*lk, be + dir*1024,
                                           4096, lk, lk, lk, 1024);
        }
        k_zero_hc<<<64,512>>>();
        float* ob = outBufs[l];
        k_enc_layer<<<dim3(16,2,4),256,enc_smem>>>(P_WhhT + (size_t)l*2*262144, ob);
        k_extract<<<32,512>>>(l);
        layerIn = ob; lk = 512;
    }
    const float* encseq = layerIn;  // g_bufA

    // ---- decoder precompute (widened tf32 MMA) ----
    k_embed_tgt<<<4032,256>>>(y, temb);
    k_mma_gemm<<<dim3(16,16),256>>>(P_Xd0, P_embd, Wih_d0, b_d0,
                                    2016, 512, 512, 1024, 2048);
    k_mma_gemm<<<dim3(4,32),256>>>(P_P, encseq, Wa, nullptr,
                                   4096, 512, 512, 512, 512);
    k_dec_init<<<32,512>>>();

    // ---- decoder loop: 6 kernels/step (layer-2 elem fused into next attn) ----
    for (int t=0; t<TDEC; t++){
        k_attn<<<32,256>>>(P_P, encseq, b_d12 + 2048, t);
        k_skinny_mma<<<dim3(32,8),256>>>(P_xc0, P_Wcat0);
        k_elem<<<32,512>>>(P_Xd0 + (size_t)t*32*2048, nullptr, P_cdec,
                           P_xc0+512, 1024, P_xc1, 1024, nullptr, 0);
        k_skinny_mma<<<dim3(32,8),256>>>(P_xc1, P_Wcat12);
        k_elem<<<32,512>>>(nullptr, b_d12, P_cdec + 32*512,
                           P_xc1+512, 1024, P_xc2, 1024, nullptr, 0);
        k_skinny_mma<<<dim3(32,8),256>>>(P_xc2, P_Wcat12 + (size_t)2048*1024);
    }
    // final layer-2 elem for t = TDEC-1 (writes Htop[62])
    k_elem<<<32,512>>>(nullptr, b_d12 + 2048, P_cdec + 2*32*512,
                       P_Htop + (size_t)(TDEC-1)*32*512, 512, nullptr, 0, nullptr, 0);

    // ---- output head: widened tf32 tensor-core GEMM, permuted store ----
    k_head_mma<<<dim3(250,16),256>>>(out, P_Htop, Wout, bout);
}

// round 16
// speedup vs baseline: 1.0355x; 1.0355x over previous
#include <cuda_runtime.h>
#include <math.h>

// Problem constants
#define S_LEN 128
#define B_SZ  32
#define D_MOD 256
#define H_SZ  512
#define T_LEN 64
#define TDEC  63
#define VT_SZ 32000

typedef unsigned long long ull;

// ---------------- packed fp32x2 helpers (encoder persistent kernel only) ----------------
__device__ __forceinline__ ull pk2(float lo, float hi){
    ull r; asm("mov.b64 %0, {%1, %2};" : "=l"(r) : "f"(lo), "f"(hi)); return r;
}
__device__ __forceinline__ void ffma2(ull &d, ull a, ull b){
    asm("fma.rn.f32x2 %0, %1, %2, %0;" : "+l"(d) : "l"(a), "l"(b));
}
__device__ __forceinline__ float2 upk(ull v){
    float2 f; asm("mov.b64 {%0, %1}, %2;" : "=f"(f.x), "=f"(f.y) : "l"(v)); return f;
}
__device__ __forceinline__ ull addp(ull a, ull b){
    ull r; asm("add.rn.f32x2 %0, %1, %2;" : "=l"(r) : "l"(a), "l"(b)); return r;
}
__device__ __forceinline__ unsigned f2tf32(float f){
    unsigned u; asm("cvt.rna.tf32.f32 %0, %1;" : "=r"(u) : "f"(f)); return u;
}

// ---------------- scratch (device globals; no allocation allowed) ----------------
__device__ float g_emb  [4096*256];
__device__ float g_bufA [4096*512];
__device__ float g_bufB [4096*512];
__device__ float g_Xg   [2*4096*1024];
__device__ float g_WhhT [6*16*256*64];
__device__ float g_he   [2][2*32*256];
__device__ float g_ce   [2*32*256];
__device__ float g_hdec [3*32*512];
__device__ float g_cdec [3*32*512];
__device__ float g_embd [2048*512];
__device__ float g_Xd0  [2048*2048];
__device__ float g_Wcat0 [2048*1024];
__device__ float g_Wcat12[2*2048*1024];
__device__ float g_P    [4096*512];
__device__ float g_xc0  [32*1024];
__device__ float g_xc1  [32*1024];
__device__ float g_xc2  [32*1024];
__device__ float g_hTop [32*512];
__device__ float g_Gp   [8*32*2048];
__device__ float g_GpB  [8*32*2048];
__device__ float g_Htop [2048*512];

__device__ unsigned int g_barc[8*32];      // encoder group barriers
__device__ unsigned int g_dbar[32];        // decoder grid barrier

__device__ __forceinline__ float sigm(float x){ return 1.f/(1.f+expf(-x)); }

// ---------------- setup kernels ----------------
__global__ void k_embed_src(const int* __restrict__ x, const float* __restrict__ emb){
    int idx = blockIdx.x*blockDim.x + threadIdx.x;
    int d = idx & 255; int sb = idx >> 8; int b = sb & 31; int s = sb >> 5;
    g_emb[idx] = emb[(size_t)x[b*S_LEN + s]*D_MOD + d];
}

__global__ void k_embed_tgt(const int* __restrict__ y, const float* __restrict__ emb){
    int idx = blockIdx.x*blockDim.x + threadIdx.x;
    int u = idx & 511; int tb = idx >> 9; int b = tb & 31; int t = tb >> 5;
    g_embd[idx] = emb[(size_t)y[b*T_LEN + t]*H_SZ + u];
}

__global__ void k_trans_whh(const float* __restrict__ we0, const float* __restrict__ we12){
    int idx = blockIdx.x*blockDim.x + threadIdx.x;
    int mat = idx >> 18; int rem = idx & 262143;
    int jt = (rem >> 14) & 15;
    int k  = (rem >> 6) & 255;
    int g  = (rem >> 4) & 3;
    int jj = rem & 15;
    int n = g*256 + jt*16 + jj;
    const float* src = (mat < 2) ? (we0 + (size_t)mat*1024*256)
                                 : (we12 + (size_t)(mat-2)*1024*256);
    g_WhhT[idx] = src[n*256 + k];
}

__global__ void k_build_wcat(const float* __restrict__ wih0, const float* __restrict__ whh0,
                             const float* __restrict__ wih12, const float* __restrict__ whh12){
    int idx = blockIdx.x*blockDim.x + threadIdx.x;
    int m = idx / (2048*1024); int rem = idx % (2048*1024);
    int n = rem >> 10; int c = rem & 1023;
    if (m == 0){
        g_Wcat0[rem] = (c < 512) ? wih0[n*1024 + 512 + c] : whh0[n*512 + (c-512)];
    } else {
        int l = m - 1;
        float v = (c < 512) ? wih12[((size_t)l*2048 + n)*512 + c]
                            : whh12[((size_t)l*2048 + n)*512 + (c-512)];
        g_Wcat12[((size_t)l*2048 + n)*1024 + c] = v;
    }
}

__global__ void k_zero_hc(){
    int i = blockIdx.x*blockDim.x + threadIdx.x;
    if (i < 2*32*256){ g_he[0][i]=0.f; g_he[1][i]=0.f; g_ce[i]=0.f; }
}

// ---------------- generalized tf32 MMA GEMM (proven R11/R14) ----------------
__global__ __launch_bounds__(256) void k_mma_gemm(
    float* __restrict__ C, const float* __restrict__ A, const float* __restrict__ W,
    const float* __restrict__ bias, int M, int K, int lda, int ldw, int ldc)
{
    __shared__ unsigned As[128*36];
    __shared__ unsigned Ws[64*36];
    int bm = blockIdx.y*128, bn = blockIdx.x*64;
    int tid = threadIdx.x;
    int lane = tid & 31, warp = tid >> 5;
    int g = lane >> 2, tig = lane & 3;
    int wm = (warp & 3)*32, wn = (warp >> 2)*32;
    float acc[2][4][4];
    #pragma unroll
    for (int mt=0;mt<2;mt++)
        #pragma unroll
        for (int nt=0;nt<4;nt++)
            #pragma unroll
            for (int q=0;q<4;q++) acc[mt][nt][q]=0.f;

    for (int kc = 0; kc < K; kc += 32){
        #pragma unroll
        for (int q=0;q<4;q++){
            int idx = tid + q*256;
            int row = idx >> 3, c4 = (idx & 7)*4;
            float4 v = make_float4(0.f,0.f,0.f,0.f);
            if (bm + row < M)
                v = *reinterpret_cast<const float4*>(A + (size_t)(bm+row)*lda + kc + c4);
            unsigned* d = As + row*36 + c4;
            d[0]=f2tf32(v.x); d[1]=f2tf32(v.y); d[2]=f2tf32(v.z); d[3]=f2tf32(v.w);
        }
        #pragma unroll
        for (int q=0;q<2;q++){
            int idx = tid + q*256;
            int row = idx >> 3, c4 = (idx & 7)*4;
            float4 v = *reinterpret_cast<const float4*>(W + (size_t)(bn+row)*ldw + kc + c4);
            unsigned* d = Ws + row*36 + c4;
            d[0]=f2tf32(v.x); d[1]=f2tf32(v.y); d[2]=f2tf32(v.z); d[3]=f2tf32(v.w);
        }
        __syncthreads();
        #pragma unroll
        for (int k8 = 0; k8 < 32; k8 += 8){
            unsigned a[2][4], bf[4][2];
            #pragma unroll
            for (int mt=0;mt<2;mt++){
                int rb = wm + mt*16;
                a[mt][0] = As[(rb+g  )*36 + k8 + tig];
                a[mt][1] = As[(rb+g+8)*36 + k8 + tig];
                a[mt][2] = As[(rb+g  )*36 + k8 + tig + 4];
                a[mt][3] = As[(rb+g+8)*36 + k8 + tig + 4];
            }
            #pragma unroll
            for (int nt=0;nt<4;nt++){
                int nb = wn + nt*8 + g;
                bf[nt][0] = Ws[nb*36 + k8 + tig];
                bf[nt][1] = Ws[nb*36 + k8 + tig + 4];
            }
            #pragma unroll
            for (int mt=0;mt<2;mt++)
                #pragma unroll
                for (int nt=0;nt<4;nt++){
                    asm("mma.sync.aligned.m16n8k8.row.col.f32.tf32.tf32.f32 "
                        "{%0,%1,%2,%3}, {%4,%5,%6,%7}, {%8,%9}, {%0,%1,%2,%3};"
                        : "+f"(acc[mt][nt][0]),"+f"(acc[mt][nt][1]),
                          "+f"(acc[mt][nt][2]),"+f"(acc[mt][nt][3])
                        : "r"(a[mt][0]),"r"(a[mt][1]),"r"(a[mt][2]),"r"(a[mt][3]),
                          "r"(bf[nt][0]),"r"(bf[nt][1]));
                }
        }
        __syncthreads();
    }
    #pragma unroll
    for (int mt=0;mt<2;mt++){
        #pragma unroll
        for (int nt=0;nt<4;nt++){
            int col = bn + wn + nt*8 + 2*tig;
            float bx = bias ? bias[col] : 0.f;
            float by = bias ? bias[col+1] : 0.f;
            int r0 = bm + wm + mt*16 + g;
            int r1 = r0 + 8;
            if (r0 < M){
                C[(size_t)r0*ldc + col]   = acc[mt][nt][0] + bx;
                C[(size_t)r0*ldc + col+1] = acc[mt][nt][1] + by;
            }
            if (r1 < M){
                C[(size_t)r1*ldc + col]   = acc[mt][nt][2] + bx;
                C[(size_t)r1*ldc + col+1] = acc[mt][nt][3] + by;
            }
        }
    }
}

// ---------------- tf32 head GEMM, 128x128 tile (proven R14), permuted store ----------------
__global__ __launch_bounds__(256) void k_head_mma(
    float* __restrict__ C, const float* __restrict__ A, const float* __restrict__ W,
    const float* __restrict__ bias)
{
    __shared__ unsigned As[128*36];
    __shared__ unsigned Ws[128*36];
    int bm = blockIdx.y*128, bn = blockIdx.x*128;
    int tid = threadIdx.x;
    int lane = tid & 31, warp = tid >> 5;
    int g = lane >> 2, tig = lane & 3;
    int wm = (warp & 3)*32, wn = (warp >> 2)*64;
    float acc[2][8][4];
    #pragma unroll
    for (int mt=0;mt<2;mt++)
        #pragma unroll
        for (int nt=0;nt<8;nt++)
            #pragma unroll
            for (int q=0;q<4;q++) acc[mt][nt][q]=0.f;

    for (int kc = 0; kc < 512; kc += 32){
        #pragma unroll
        for (int q=0;q<4;q++){
            int idx = tid + q*256;
            int row = idx >> 3, c4 = (idx & 7)*4;
            float4 v = make_float4(0.f,0.f,0.f,0.f);
            if (bm + row < 2016)
                v = *reinterpret_cast<const float4*>(A + (size_t)(bm+row)*512 + kc + c4);
            unsigned* d = As + row*36 + c4;
            d[0]=f2tf32(v.x); d[1]=f2tf32(v.y); d[2]=f2tf32(v.z); d[3]=f2tf32(v.w);
        }
        #pragma unroll
        for (int q=0;q<4;q++){
            int idx = tid + q*256;
            int row = idx >> 3, c4 = (idx & 7)*4;
            float4 v = *reinterpret_cast<const float4*>(W + (size_t)(bn+row)*512 + kc + c4);
            unsigned* d = Ws + row*36 + c4;
            d[0]=f2tf32(v.x); d[1]=f2tf32(v.y); d[2]=f2tf32(v.z); d[3]=f2tf32(v.w);
        }
        __syncthreads();
        #pragma unroll
        for (int k8 = 0; k8 < 32; k8 += 8){
            unsigned a[2][4], bf[8][2];
            #pragma unroll
            for (int mt=0;mt<2;mt++){
                int rb = wm + mt*16;
                a[mt][0] = As[(rb+g  )*36 + k8 + tig];
                a[mt][1] = As[(rb+g+8)*36 + k8 + tig];
                a[mt][2] = As[(rb+g  )*36 + k8 + tig + 4];
                a[mt][3] = As[(rb+g+8)*36 + k8 + tig + 4];
            }
            #pragma unroll
            for (int nt=0;nt<8;nt++){
                int nb = wn + nt*8 + g;
                bf[nt][0] = Ws[nb*36 + k8 + tig];
                bf[nt][1] = Ws[nb*36 + k8 + tig + 4];
            }
            #pragma unroll
            for (int mt=0;mt<2;mt++)
                #pragma unroll
                for (int nt=0;nt<8;nt++){
                    asm("mma.sync.aligned.m16n8k8.row.col.f32.tf32.tf32.f32 "
                        "{%0,%1,%2,%3}, {%4,%5,%6,%7}, {%8,%9}, {%0,%1,%2,%3};"
                        : "+f"(acc[mt][nt][0]),"+f"(acc[mt][nt][1]),
                          "+f"(acc[mt][nt][2]),"+f"(acc[mt][nt][3])
                        : "r"(a[mt][0]),"r"(a[mt][1]),"r"(a[mt][2]),"r"(a[mt][3]),
                          "r"(bf[nt][0]),"r"(bf[nt][1]));
                }
        }
        __syncthreads();
    }
    #pragma unroll
    for (int mt=0;mt<2;mt++){
        #pragma unroll
        for (int nt=0;nt<8;nt++){
            int col = bn + wn + nt*8 + 2*tig;
            float bx = bias[col], by = bias[col+1];
            int r0 = bm + wm + mt*16 + g;
            int r1 = r0 + 8;
            if (r0 < 2016){
                int rr = (r0 & 31)*TDEC + (r0 >> 5);
                C[(size_t)rr*VT_SZ + col]   = acc[mt][nt][0] + bx;
                C[(size_t)rr*VT_SZ + col+1] = acc[mt][nt][1] + by;
            }
            if (r1 < 2016){
                int rr = (r1 & 31)*TDEC + (r1 >> 5);
                C[(size_t)rr*VT_SZ + col]   = acc[mt][nt][2] + bx;
                C[(size_t)rr*VT_SZ + col+1] = acc[mt][nt][3] + by;
            }
        }
    }
}

// ---------------- persistent encoder layer (proven R5) ----------------
#define ENC_SMEM_FLOATS (16384 + 2048 + 2048 + 512)
__global__ __launch_bounds__(256) void k_enc_layer(const float* __restrict__ WT,
                                                   float* __restrict__ out)
{
    extern __shared__ float dyn[];
    float* ws   = dyn;
    float* hstf = dyn + 16384;
    ull*   psum = (ull*)(dyn + 16384 + 2048);
    float* sgf  = dyn + 16384 + 2048 + 2048;

    int jt = blockIdx.x, dir = blockIdx.y, bb = blockIdx.z;
    int tid = threadIdx.x;
    const float* Wg = WT + (size_t)dir*262144 + (size_t)jt*16384;
    for (int i = tid; i < 16384; i += 256) ws[i] = Wg[i];

    int gid = dir*4 + bb;
    unsigned* bcnt = &g_barc[gid*32];
    volatile unsigned* bgen = (volatile unsigned*)&g_barc[gid*32 + 16];

    int col1 = tid & 63, kq = tid >> 6;
    int col2 = tid >> 2, pr = tid & 3;
    int jj = tid >> 3, b = tid & 7;
    int bglob = bb*8 + b;
    int j = jt*16 + jj;
    float creg = 0.f;
    __syncthreads();

    for (int t = 0; t < S_LEN; t++){
        int cur = t & 1, nxt = cur ^ 1;
        int tt = dir ? (S_LEN-1-t) : t;
        #pragma unroll
        for (int q = 0; q < 8; q++){
            hstf[tid*8 + q] = __ldcg(&g_he[cur][(dir*32 + bb*8 + q)*256 + tid]);
        }
        __syncthreads();
        {
            const float* wp = ws + col1;
            const ulonglong2* hp = (const ulonglong2*)hstf;
            ull a0=0,a1=0,a2=0,a3=0;
            #pragma unroll 8
            for (int kk = 0; kk < 64; kk++){
                int k = kq*64 + kk;
                float w = wp[k*64];
                ull w2 = pk2(w, w);
                ulonglong2 hA = hp[k*2], hB = hp[k*2+1];
                ffma2(a0, w2, hA.x); ffma2(a1, w2, hA.y);
                ffma2(a2, w2, hB.x); ffma2(a3, w2, hB.y);
            }
            ull* pp = psum + ((size_t)kq*64 + col1)*4;
            pp[0]=a0; pp[1]=a1; pp[2]=a2; pp[3]=a3;
        }
        __syncthreads();
        {
            ull s = psum[(0*64+col2)*4+pr];
            s = addp(s, psum[(1*64+col2)*4+pr]);
            s = addp(s, psum[(2*64+col2)*4+pr]);
            s = addp(s, psum[(3*64+col2)*4+pr]);
            ((ull*)sgf)[col2*4+pr] = s;
        }
        __syncthreads();
        if (tid < 128){
            float gi = sgf[(0*16+jj)*8 + b];
            float gf = sgf[(1*16+jj)*8 + b];
            float gg = sgf[(2*16+jj)*8 + b];
            float go = sgf[(3*16+jj)*8 + b];
            const float* xg = g_Xg + ((size_t)(dir*S_LEN + tt)*32 + bglob)*1024;
            gi += xg[j]; gf += xg[256+j]; gg += xg[512+j]; go += xg[768+j];
            float c2 = sigm(gf)*creg + sigm(gi)*tanhf(gg);
            float h2 = sigm(go)*tanhf(c2);
            creg = c2;
            __stcg(&g_he[nxt][(dir*32+bglob)*256 + j], h2);
            out[((size_t)tt*32 + bglob)*512 + dir*256 + j] = h2;
        }
        __threadfence();
        __syncthreads();
        if (tid == 0){
            unsigned gen = *bgen;
            if (atomicAdd(bcnt, 1u) == 15u){
                *bcnt = 0;
                __threadfence();
                *bgen = gen + 1u;
            } else {
                while (*bgen == gen) __nanosleep(32);
            }
        }
        __syncthreads();
    }
    if (tid < 128) g_ce[(dir*32+bglob)*256 + j] = creg;
}

__global__ void k_extract(int l){
    int b = blockIdx.x, tid = threadIdx.x;
    int dir = tid >> 8, jj = tid & 255;
    g_hdec[((size_t)l*32 + b)*512 + tid] = g_he[0][(dir*32+b)*256 + jj];
    g_cdec[((size_t)l*32 + b)*512 + tid] = g_ce[(dir*32+b)*256 + jj];
}

__global__ void k_dec_init(){
    int b = blockIdx.x, u = threadIdx.x;
    g_xc0[b*1024 + 512 + u] = g_hdec[(0*32+b)*512 + u];
    g_xc1[b*1024 + 512 + u] = g_hdec[(1*32+b)*512 + u];
    float h2 = g_hdec[(2*32+b)*512 + u];
    g_xc2[b*1024 + 512 + u] = h2;
    g_hTop[b*512 + u] = h2;
    if (b == 0 && u < 32) g_dbar[u] = 0;
}

// ---------------- persistent decoder: all 63 steps, one launch ----------------
// 256 blocks (ntile = bid&31, p = bid>>5), 2 blocks/SM (co-residency guaranteed).
// Weights for all 3 layers resident in smem as tf32; phases separated by grid barrier.
#define DEC_SMEM_BYTES ((3*4*64*33 + 32*36)*4)

__device__ __forceinline__ void gridbar256(){
    __threadfence();
    __syncthreads();
    if (threadIdx.x == 0){
        volatile unsigned* bgen = (volatile unsigned*)&g_dbar[16];
        unsigned gen = *bgen;
        if (atomicAdd(&g_dbar[0], 1u) == 255u){
            g_dbar[0] = 0;
            __threadfence();
            *bgen = gen + 1u;
        } else {
            while (*bgen == gen) __nanosleep(32);
        }
    }
    __syncthreads();
}

// elem for one batch b over 512 units (256 threads, 2 units each)
__device__ __forceinline__ void dec_elem(const float* __restrict__ Gp,
                                         const float* __restrict__ add,
                                         const float* __restrict__ bias,
                                         float* __restrict__ c,
                                         float* __restrict__ d1,
                                         float* __restrict__ d2,
                                         float* __restrict__ hsh,
                                         int b, int tid)
{
    for (int u = tid; u < 512; u += 256){
        float gi=0.f, gf=0.f, gg=0.f, go=0.f;
        #pragma unroll
        for (int pp=0; pp<8; pp++){
            const float* gp = Gp + (size_t)(pp*32+b)*2048;
            gi += gp[u]; gf += gp[512+u]; gg += gp[1024+u]; go += gp[1536+u];
        }
        if (add){ gi+=add[u]; gf+=add[512+u]; gg+=add[1024+u]; go+=add[1536+u]; }
        if (bias){ gi+=bias[u]; gf+=bias[512+u]; gg+=bias[1024+u]; go+=bias[1536+u]; }
        float cv = c[b*512 + u];
        float c2 = sigm(gf)*cv + sigm(gi)*tanhf(gg);
        float h2 = sigm(go)*tanhf(c2);
        c[b*512 + u] = c2;
        if (d1) d1[u] = h2;
        if (d2) d2[u] = h2;
        if (hsh) hsh[u] = h2;
    }
}

// one layer's K-split MMA using resident weights
__device__ __forceinline__ void dec_mma_phase(const float* __restrict__ A,
                                              const unsigned* __restrict__ Wres,
                                              float* __restrict__ Gp,
                                              unsigned* As, int tid, int n0, int p)
{
    int lane = tid & 31, warp = tid >> 5;
    int g = lane >> 2, tig = lane & 3;
    int k0 = p*128;
    float acc[2][4];
    #pragma unroll
    for (int mt=0;mt<2;mt++){ acc[mt][0]=0.f; acc[mt][1]=0.f; acc[mt][2]=0.f; acc[mt][3]=0.f; }
    #pragma unroll 1
    for (int ch=0; ch<4; ch++){
        {
            int row = tid >> 3, c4 = (tid & 7)*4;
            float4 v = *reinterpret_cast<const float4*>(A + (size_t)row*1024 + k0 + ch*32 + c4);
            unsigned* d = As + row*36 + c4;
            d[0]=f2tf32(v.x); d[1]=f2tf32(v.y); d[2]=f2tf32(v.z); d[3]=f2tf32(v.w);
        }
        __syncthreads();
        const unsigned* Wc = Wres + ch*(64*33);
        #pragma unroll
        for (int k8 = 0; k8 < 32; k8 += 8){
            unsigned a[2][4], bf[2];
            #pragma unroll
            for (int mt=0;mt<2;mt++){
                int rb = mt*16;
                a[mt][0] = As[(rb+g  )*36 + k8 + tig];
                a[mt][1] = As[(rb+g+8)*36 + k8 + tig];
                a[mt][2] = As[(rb+g  )*36 + k8 + tig + 4];
                a[mt][3] = As[(rb+g+8)*36 + k8 + tig + 4];
            }
            int nb = warp*8 + g;
            bf[0] = Wc[nb*33 + k8 + tig];
            bf[1] = Wc[nb*33 + k8 + tig + 4];
            #pragma unroll
            for (int mt=0;mt<2;mt++){
                asm("mma.sync.aligned.m16n8k8.row.col.f32.tf32.tf32.f32 "
                    "{%0,%1,%2,%3}, {%4,%5,%6,%7}, {%8,%9}, {%0,%1,%2,%3};"
                    : "+f"(acc[mt][0]),"+f"(acc[mt][1]),
                      "+f"(acc[mt][2]),"+f"(acc[mt][3])
                    : "r"(a[mt][0]),"r"(a[mt][1]),"r"(a[mt][2]),"r"(a[mt][3]),
                      "r"(bf[0]),"r"(bf[1]));
            }
        }
        __syncthreads();
    }
    float* outp = Gp + (size_t)p*32*2048;
    int colg = n0 + warp*8 + 2*tig;
    #pragma unroll
    for (int mt=0;mt<2;mt++){
        int r0 = mt*16 + g;
        outp[(size_t)r0*2048 + colg]       = acc[mt][0];
        outp[(size_t)r0*2048 + colg+1]     = acc[mt][1];
        outp[(size_t)(r0+8)*2048 + colg]   = acc[mt][2];
        outp[(size_t)(r0+8)*2048 + colg+1] = acc[mt][3];
    }
}

__global__ __launch_bounds__(256, 2) void k_dec_persist(
    const float* __restrict__ P, const float* __restrict__ enc,
    const float* __restrict__ Wc0, const float* __restrict__ Wc12,
    const float* __restrict__ Xd0, const float* __restrict__ bd12)
{
    extern __shared__ float smf[];
    unsigned* Wsm = (unsigned*)smf;            // [3][4][64*33]
    unsigned* As  = Wsm + 3*4*64*33;           // [32*36]
    float* attnbuf = (float*)As;               // hsh[512] | ssh[128] | red[12]

    int bid = blockIdx.x;
    int ntile = bid & 31, p = bid >> 5;
    int tid = threadIdx.x;
    int n0 = ntile*64, k0 = p*128;

    // load resident weights (tf32 converted)
    for (int lay=0; lay<3; lay++){
        const float* Wl = (lay==0) ? Wc0 : (Wc12 + (size_t)(lay-1)*2048*1024);
        const float* Wb = Wl + (size_t)n0*1024 + k0;
        unsigned* dst = Wsm + lay*(4*64*33);
        for (int i = tid; i < 8192; i += 256){
            int ch = i >> 11, rem = i & 2047;
            int row = rem >> 5, c = rem & 31;
            dst[ch*(64*33) + row*33 + c] = f2tf32(Wb[(size_t)row*1024 + ch*32 + c]);
        }
    }
    __syncthreads();

    for (int t = 0; t <= TDEC; t++){
        // ---- Phase A: elem2(t-1) + attention(t)  [blocks 0..31] ----
        if (bid < 32){
            int b = bid;
            float* hsh = attnbuf;
            float* ssh = attnbuf + 512;
            float* red = attnbuf + 640;
            if (t > 0){
                dec_elem(g_Gp, nullptr, bd12 + 2048, g_cdec + 2*32*512,
                         g_Htop + ((size_t)(t-1)*32 + b)*512,
                         g_xc2 + b*1024 + 512, hsh, b, tid);
            } else {
                hsh[tid]     = g_hTop[b*512 + tid];
                hsh[256+tid] = g_hTop[b*512 + 256 + tid];
            }
            __syncthreads();
            if (t < TDEC){
                int warp = tid >> 5, lane = tid & 31;
                for (int s = warp; s < 128; s += 8){
                    const float* pp = P + ((size_t)s*32 + b)*512;
                    float acc = 0.f;
                    for (int i = lane; i < 512; i += 32) acc += hsh[i]*pp[i];
                    #pragma unroll
                    for (int o=16;o>0;o>>=1) acc += __shfl_xor_sync(0xffffffffu, acc, o);
                    if (lane == 0) ssh[s] = acc;
                }
                __syncthreads();
                float m = -1e30f;
                if (tid < 128) m = ssh[tid];
                #pragma unroll
                for (int o=16;o>0;o>>=1) m = fmaxf(m, __shfl_xor_sync(0xffffffffu, m, o));
                if (tid < 128 && lane == 0) red[warp] = m;
                __syncthreads();
                float mx = fmaxf(fmaxf(red[0],red[1]), fmaxf(red[2],red[3]));
                float ev = (tid < 128) ? expf(ssh[tid] - mx) : 0.f;
                float sum = ev;
                #pragma unroll
                for (int o=16;o>0;o>>=1) sum += __shfl_xor_sync(0xffffffffu, sum, o);
                if (tid < 128 && lane == 0) red[8+warp] = sum;
                __syncthreads();
                float tot = red[8]+red[9]+red[10]+red[11];
                if (tid < 128) ssh[tid] = ev / tot;
                __syncthreads();
                float c0=0.f, c1=0.f;
                for (int s=0;s<128;s++){
                    float a = ssh[s];
                    const float* e = enc + ((size_t)s*32 + b)*512;
                    c0 += a*e[tid]; c1 += a*e[256+tid];
                }
                g_xc0[b*1024 + tid]       = c0;
                g_xc0[b*1024 + 256 + tid] = c1;
            }
        }
        gridbar256();
        if (t == TDEC) break;

        // ---- Phase B: layer-0 MMA -> g_Gp ----
        dec_mma_phase(g_xc0, Wsm, g_Gp, As, tid, n0, p);
        gridbar256();

        // ---- Phase E0: elem0 [blocks 32..63] ----
        if (bid >= 32 && bid < 64){
            int b = bid - 32;
            dec_elem(g_Gp, Xd0 + ((size_t)t*32 + b)*2048, nullptr, g_cdec,
                     g_xc1 + b*1024, g_xc0 + b*1024 + 512, nullptr, b, tid);
        }
        gridbar256();

        // ---- Phase C: layer-1 MMA -> g_GpB ----
        dec_mma_phase(g_xc1, Wsm + 4*64*33, g_GpB, As, tid, n0, p);
        gridbar256();

        // ---- Phase E1: elem1 [blocks 64..95] ----
        if (bid >= 64 && bid < 96){
            int b = bid - 64;
            dec_elem(g_GpB, nullptr, bd12, g_cdec + 32*512,
                     g_xc2 + b*1024, g_xc1 + b*1024 + 512, nullptr, b, tid);
        }
        gridbar256();

        // ---- Phase D: layer-2 MMA -> g_Gp ----
        dec_mma_phase(g_xc2, Wsm + 8*64*33, g_Gp, As, tid, n0, p);
        gridbar256();
    }
}

// ---------------- host orchestration ----------------
static float* symaddr(const void* s){ void* p=nullptr; cudaGetSymbolAddress(&p, s); return (float*)p; }

extern "C" void kernel_launch(void* const* d_in, const int* in_sizes, int n_in,
                              void* d_out, int out_size)
{
    (void)in_sizes; (void)n_in; (void)out_size;
    const int*   x       = (const int*)  d_in[0];
    const int*   y       = (const int*)  d_in[1];
    const float* semb    = (const float*)d_in[2];
    const float* temb    = (const float*)d_in[3];
    const float* Wih_e0  = (const float*)d_in[4];
    const float* Whh_e0  = (const float*)d_in[5];
    const float* b_e0    = (const float*)d_in[6];
    const float* Wih_e12 = (const float*)d_in[7];
    const float* Whh_e12 = (const float*)d_in[8];
    const float* b_e12   = (const float*)d_in[9];
    const float* Wih_d0  = (const float*)d_in[10];
    const float* Whh_d0  = (const float*)d_in[11];
    const float* b_d0    = (const float*)d_in[12];
    const float* Wih_d12 = (const float*)d_in[13];
    const float* Whh_d12 = (const float*)d_in[14];
    const float* b_d12   = (const float*)d_in[15];
    const float* Wa      = (const float*)d_in[16];
    const float* Wout    = (const float*)d_in[17];
    const float* bout    = (const float*)d_in[18];
    float* out = (float*)d_out;

    float* P_emb   = symaddr(g_emb);
    float* P_bufA  = symaddr(g_bufA);
    float* P_bufB  = symaddr(g_bufB);
    float* P_Xg    = symaddr(g_Xg);
    float* P_WhhT  = symaddr(g_WhhT);
    float* P_embd  = symaddr(g_embd);
    float* P_Xd0   = symaddr(g_Xd0);
    float* P_Wcat0 = symaddr(g_Wcat0);
    float* P_Wcat12= symaddr(g_Wcat12);
    float* P_P     = symaddr(g_P);
    float* P_Htop  = symaddr(g_Htop);

    const int enc_smem = ENC_SMEM_FLOATS * 4;
    cudaFuncSetAttribute(k_enc_layer, cudaFuncAttributeMaxDynamicSharedMemorySize, enc_smem);
    cudaFuncSetAttribute(k_dec_persist, cudaFuncAttributeMaxDynamicSharedMemorySize, DEC_SMEM_BYTES);

    // ---- setup ----
    k_trans_whh<<<6144,256>>>(Whh_e0, Whh_e12);
    k_build_wcat<<<24576,256>>>(Wih_d0, Whh_d0, Wih_d12, Whh_d12);
    k_embed_src<<<4096,256>>>(x, semb);

    // ---- encoder: 3 bidirectional layers (Xg via tf32 MMA) ----
    const float* layerIn = P_emb; int lk = 256;
    float* outBufs[3] = {P_bufA, P_bufB, P_bufA};
    for (int l=0; l<3; l++){
        const float* Wih = (l==0) ? Wih_e0 : (Wih_e12 + (size_t)(l-1)*2*1024*512);
        const float* be  = (l==0) ? b_e0   : (b_e12  + (size_t)(l-1)*2*1024);
        for (int dir=0; dir<2; dir++){
            k_mma_gemm<<<dim3(16,32),256>>>(P_Xg + (size_t)dir*4096*1024, layerIn,
                                            Wih + (size_t)dir*1024*lk, be + dir*1024,
                                            4096, lk, lk, lk, 1024);
        }
        k_zero_hc<<<64,512>>>();
        float* ob = outBufs[l];
        k_enc_layer<<<dim3(16,2,4),256,enc_smem>>>(P_WhhT + (size_t)l*2*262144, ob);
        k_extract<<<32,512>>>(l);
        layerIn = ob; lk = 512;
    }
    const float* encseq = layerIn;  // g_bufA

    // ---- decoder precompute (tf32 MMA) ----
    k_embed_tgt<<<4032,256>>>(y, temb);
    k_mma_gemm<<<dim3(32,16),256>>>(P_Xd0, P_embd, Wih_d0, b_d0,
                                    2016, 512, 512, 1024, 2048);
    k_mma_gemm<<<dim3(8,32),256>>>(P_P, encseq, Wa, nullptr,
                                   4096, 512, 512, 512, 512);
    k_dec_init<<<32,512>>>();

    // ---- decoder: single persistent kernel, weights resident in smem ----
    k_dec_persist<<<256,256,DEC_SMEM_BYTES>>>(P_P, encseq, P_Wcat0, P_Wcat12,
                                              P_Xd0, b_d12);

    // ---- output head: widened tf32 tensor-core GEMM, permuted store ----
    k_head_mma<<<dim3(250,16),256>>>(out, P_Htop, Wout, bout);
}